// round 1
// baseline (speedup 1.0000x reference)
#include <cuda_runtime.h>
#include <math.h>

#define NN 100000
#define NE 1600000
#define DIM 64

typedef unsigned long long u64t;

// -------- scratch (static device globals; no runtime allocation) --------
__device__ float d_Q[(size_t)NN * DIM];   // 25.6 MB
__device__ float d_K[(size_t)NN * DIM];   // 25.6 MB
__device__ float d_g[NN];                 // per-node gate scalar
__device__ float d_denom[NN];             // softmax denominators
__device__ float d_wvf[DIM];              // Wv @ wF
__device__ float d_c2;                    // bv·wF + bF

// -------- helpers --------
__device__ __forceinline__ float silu_f(float z) {
    // z * sigmoid(z) = z / (1 + exp(-z))
    return __fdividef(z, 1.0f + __expf(-z));
}

__device__ __forceinline__ u64t pack2(float v) {
    u64t r;
    unsigned u = __float_as_uint(v);
    asm("mov.b64 %0, {%1, %2};" : "=l"(r) : "r"(u), "r"(u));
    return r;
}

__device__ __forceinline__ void ffma2(u64t& d, u64t a, u64t b) {
    // packed f32x2 FMA: 2 fp32 MACs per instruction (sm_103a)
    asm("fma.rn.f32x2 %0, %1, %2, %0;" : "+l"(d) : "l"(a), "l"(b));
}

__device__ __forceinline__ float2 unpack2(u64t v) {
    unsigned lo, hi;
    asm("mov.b64 {%0, %1}, %2;" : "=r"(lo), "=r"(hi) : "l"(v));
    return make_float2(__uint_as_float(lo), __uint_as_float(hi));
}

// -------- K0: zero accumulators, fold Wv@wF --------
__global__ void k_init(const float* __restrict__ Wv, const float* __restrict__ bv,
                       const float* __restrict__ wF, const float* __restrict__ bF,
                       float* __restrict__ out) {
    int t = blockIdx.x * blockDim.x + threadIdx.x;
    if (t < NN) d_denom[t] = 0.0f;
    if (t < 3 * NN) out[t] = 0.0f;
    if (blockIdx.x == 0 && threadIdx.x < DIM) {
        int c = threadIdx.x;
        float s = 0.0f;
        for (int d = 0; d < DIM; ++d) s += Wv[c * DIM + d] * wF[d];
        d_wvf[c] = s;
        if (c == 0) {
            float s2 = bF[0];
            for (int d = 0; d < DIM; ++d) s2 += bv[d] * wF[d];
            d_c2 = s2;
        }
    }
}

// -------- K1: per-node Q, K projections + gate scalar --------
__global__ void __launch_bounds__(256) k_nodes(
    const float* __restrict__ x,
    const float* __restrict__ Wq, const float* __restrict__ bq,
    const float* __restrict__ Wk, const float* __restrict__ bk) {

    __shared__ __align__(16) float sWq[DIM * DIM];
    __shared__ __align__(16) float sWk[DIM * DIM];
    __shared__ __align__(16) float sbq[DIM];
    __shared__ __align__(16) float sbk[DIM];
    __shared__ __align__(16) float swvf[DIM];

    for (int idx = threadIdx.x; idx < DIM * DIM; idx += blockDim.x) {
        sWq[idx] = Wq[idx];
        sWk[idx] = Wk[idx];
    }
    if (threadIdx.x < DIM) {
        sbq[threadIdx.x]  = bq[threadIdx.x];
        sbk[threadIdx.x]  = bk[threadIdx.x];
        swvf[threadIdx.x] = d_wvf[threadIdx.x];
    }
    __syncthreads();

    int n = blockIdx.x * blockDim.x + threadIdx.x;
    if (n >= NN) return;

    // x row -> registers
    float xv[DIM];
    const float4* xr = (const float4*)(x + (size_t)n * DIM);
#pragma unroll
    for (int c4 = 0; c4 < 16; ++c4) {
        float4 t = xr[c4];
        xv[4 * c4 + 0] = t.x; xv[4 * c4 + 1] = t.y;
        xv[4 * c4 + 2] = t.z; xv[4 * c4 + 3] = t.w;
    }

    // gate scalar
    float g = d_c2;
#pragma unroll
    for (int c = 0; c < DIM; ++c) g = fmaf(xv[c], swvf[c], g);
    d_g[n] = g;

    float* qout = d_Q + (size_t)n * DIM;
    float* kout = d_K + (size_t)n * DIM;

    // 16 output dims per pass to bound register pressure
    for (int db = 0; db < 4; ++db) {
        float aq[16], ak[16];
#pragma unroll
        for (int t = 0; t < 16; ++t) {
            aq[t] = sbq[16 * db + t];
            ak[t] = sbk[16 * db + t];
        }
#pragma unroll
        for (int c = 0; c < DIM; ++c) {
            float xc = xv[c];
            const float* wq = sWq + c * DIM + 16 * db;
            const float* wk = sWk + c * DIM + 16 * db;
#pragma unroll
            for (int t = 0; t < 16; ++t) {
                aq[t] = fmaf(xc, wq[t], aq[t]);
                ak[t] = fmaf(xc, wk[t], ak[t]);
            }
        }
#pragma unroll
        for (int t4 = 0; t4 < 4; ++t4) {
            *(float4*)(qout + 16 * db + 4 * t4) =
                make_float4(aq[4 * t4], aq[4 * t4 + 1], aq[4 * t4 + 2], aq[4 * t4 + 3]);
            *(float4*)(kout + 16 * db + 4 * t4) =
                make_float4(ak[4 * t4], ak[4 * t4 + 1], ak[4 * t4 + 2], ak[4 * t4 + 3]);
        }
    }
}

// -------- K2: per-edge MLP + q·k + exp + scatter-add --------
__global__ void __launch_bounds__(256) k_edges(
    const float* __restrict__ edge_vec,
    const int*   __restrict__ eidx,
    const float* __restrict__ W1, const float* __restrict__ b1,
    const float* __restrict__ W2, const float* __restrict__ b2,
    const float* __restrict__ W3, const float* __restrict__ b3,
    float* __restrict__ out) {

    __shared__ __align__(16) float sW2[DIM * DIM];  // [k][d], d contiguous
    __shared__ __align__(16) float sW1T[DIM * 4];   // [k][c], c contiguous
    __shared__ __align__(16) float sb1[DIM];
    __shared__ __align__(16) float sb2[DIM];
    __shared__ __align__(16) float sW3[DIM];

    for (int idx = threadIdx.x; idx < DIM * DIM; idx += blockDim.x) sW2[idx] = W2[idx];
    if (threadIdx.x < DIM) {
        int k = threadIdx.x;
        sW1T[4 * k + 0] = W1[0 * DIM + k];
        sW1T[4 * k + 1] = W1[1 * DIM + k];
        sW1T[4 * k + 2] = W1[2 * DIM + k];
        sW1T[4 * k + 3] = W1[3 * DIM + k];
        sb1[k] = b1[k];
        sb2[k] = b2[k];
        sW3[k] = W3[k];
    }
    __syncthreads();

    const float b3v = b3[0];
    const int lane = threadIdx.x & 31;
    const int warp_global = (blockIdx.x * blockDim.x + threadIdx.x) >> 5;
    const int nwarps = (gridDim.x * blockDim.x) >> 5;
    const int ntiles = NE / 32;   // NE divisible by 32

    for (int tile = warp_global; tile < ntiles; tile += nwarps) {
        int e  = tile * 32 + lane;      // this lane's edge
        int ii = eidx[e];               // source node i
        int jj = eidx[NE + e];          // target node j

        // ---- warp-cooperative q[j]·k[i] (coalesced 8B/lane row loads) ----
        float dotv = 0.0f;
#pragma unroll 8
        for (int t = 0; t < 32; ++t) {
            int je = __shfl_sync(0xffffffffu, jj, t);
            int ie = __shfl_sync(0xffffffffu, ii, t);
            float2 q2 = *(const float2*)(d_Q + (size_t)je * DIM + 2 * lane);
            float2 k2 = *(const float2*)(d_K + (size_t)ie * DIM + 2 * lane);
            float p = fmaf(q2.y, k2.y, q2.x * k2.x);
            p += __shfl_xor_sync(0xffffffffu, p, 16);
            p += __shfl_xor_sync(0xffffffffu, p, 8);
            p += __shfl_xor_sync(0xffffffffu, p, 4);
            p += __shfl_xor_sync(0xffffffffu, p, 2);
            p += __shfl_xor_sync(0xffffffffu, p, 1);
            if (lane == t) dotv = p;
        }

        // ---- edge attr ----
        float v0 = edge_vec[3 * e + 0];
        float v1 = edge_vec[3 * e + 1];
        float v2 = edge_vec[3 * e + 2];
        float len = sqrtf(fmaf(v0, v0, fmaf(v1, v1, v2 * v2)));

        // ---- fused MLP: h1[k] computed inline, layer-2 in packed f32x2 ----
        u64t acc[32];                              // 64 output dims as f32x2 pairs
        const ulonglong2* b2p = (const ulonglong2*)sb2;
#pragma unroll
        for (int t2 = 0; t2 < 16; ++t2) {
            ulonglong2 b = b2p[t2];
            acc[2 * t2 + 0] = b.x;
            acc[2 * t2 + 1] = b.y;
        }
#pragma unroll 4
        for (int k = 0; k < DIM; ++k) {
            float4 w1r = *(const float4*)(sW1T + 4 * k);
            float z = sb1[k];
            z = fmaf(v0, w1r.x, z);
            z = fmaf(v1, w1r.y, z);
            z = fmaf(v2, w1r.z, z);
            z = fmaf(len, w1r.w, z);
            u64t h2 = pack2(silu_f(z));
            const ulonglong2* wr = (const ulonglong2*)(sW2 + k * DIM);
#pragma unroll
            for (int t2 = 0; t2 < 16; ++t2) {
                ulonglong2 w = wr[t2];
                ffma2(acc[2 * t2 + 0], h2, w.x);
                ffma2(acc[2 * t2 + 1], h2, w.y);
            }
        }

        // ---- silu + layer-3 reduction ----
        float bias = b3v;
#pragma unroll
        for (int t = 0; t < 32; ++t) {
            float2 hv = unpack2(acc[t]);
            bias = fmaf(silu_f(hv.x), sW3[2 * t + 0], bias);
            bias = fmaf(silu_f(hv.y), sW3[2 * t + 1], bias);
        }

        // ---- score, exp (scores bounded -> no max subtraction needed) ----
        float score = fmaf(dotv, 0.125f, bias);   // 1/sqrt(64)
        float ex = __expf(score);
        float w  = ex * d_g[ii];

        atomicAdd(&d_denom[jj], ex);
        atomicAdd(out + 3 * jj + 0, w * v0);
        atomicAdd(out + 3 * jj + 1, w * v1);
        atomicAdd(out + 3 * jj + 2, w * v2);
    }
}

// -------- K3: normalize --------
__global__ void k_final(float* __restrict__ out) {
    int n = blockIdx.x * blockDim.x + threadIdx.x;
    if (n < NN) {
        float r = __fdividef(1.0f, d_denom[n] + 1e-16f);
        out[3 * n + 0] *= r;
        out[3 * n + 1] *= r;
        out[3 * n + 2] *= r;
    }
}

// -------- launch --------
extern "C" void kernel_launch(void* const* d_in, const int* in_sizes, int n_in,
                              void* d_out, int out_size) {
    const float* x        = (const float*)d_in[0];
    const float* edge_vec = (const float*)d_in[1];
    const float* Wq = (const float*)d_in[2];
    const float* bq = (const float*)d_in[3];
    const float* Wk = (const float*)d_in[4];
    const float* bk = (const float*)d_in[5];
    const float* Wv = (const float*)d_in[6];
    const float* bv = (const float*)d_in[7];
    const float* W1 = (const float*)d_in[8];
    const float* b1 = (const float*)d_in[9];
    const float* W2 = (const float*)d_in[10];
    const float* b2 = (const float*)d_in[11];
    const float* W3 = (const float*)d_in[12];
    const float* b3 = (const float*)d_in[13];
    const float* wF = (const float*)d_in[14];
    const float* bF = (const float*)d_in[15];
    const int*   ei = (const int*)d_in[16];
    float* out = (float*)d_out;

    k_init <<<(3 * NN + 255) / 256, 256>>>(Wv, bv, wF, bF, out);
    k_nodes<<<(NN + 255) / 256, 256>>>(x, Wq, bq, Wk, bk);
    k_edges<<<1184, 256>>>(edge_vec, ei, W1, b1, W2, b2, W3, b3, out);
    k_final<<<(NN + 255) / 256, 256>>>(out);
}